// round 15
// baseline (speedup 1.0000x reference)
#include <cuda_runtime.h>
#include <cuda_fp16.h>
#include <cstdint>

// Packed-varlen (SEG=1024) causal attention + additive bias, fp32 I/O.
// Round 12: software-pipelined — PV runs one k-tile behind QK and its
// mma/ldsm stream is interleaved into QK's phase loop (independent work for
// the tensor pipe during what used to be serial phases). fp16 1-product QK
// and PV, p rounded once (consistent numerator/denominator). K,V double-buf.

#define SQ   2048
#define NB   2
#define NHD  16
#define HD   128
#define SEG  1024
#define BM   64
#define BN   64
#define NT   128
#define ROWSTRIDE (NB*NHD*HD)
#define ATTN_SCALE 0.08838834764831845f

// scratch: fp16 hi rows, 256B per (b,h,s)
__device__ __align__(256) static unsigned char KH[(size_t)NB * NHD * SQ * 256];
__device__ __align__(256) static unsigned char VH[(size_t)NB * NHD * SQ * 256];

#define TSTR 272
#define TILE_H 17408
#define SM_K 0                 // K double buffer: 2 x 17408
#define SM_V 34816             // V double buffer: 2 x 17408 (Q staging aliases)
#define SM_QSTG 34816
#define SMEM_TOTAL 69632       // 68 KB -> 2 CTAs/SM

__device__ __forceinline__ uint32_t s2u(const void* p) {
    uint32_t a;
    asm("{ .reg .u64 t; cvta.to.shared.u64 t, %1; cvt.u32.u64 %0, t; }" : "=r"(a) : "l"(p));
    return a;
}
__device__ __forceinline__ uint32_t pack2h(float a, float b) {
    __half ah = __float2half_rn(a);
    __half bh = __float2half_rn(b);
    return ((uint32_t)__half_as_ushort(bh) << 16) | __half_as_ushort(ah);
}
__device__ __forceinline__ void ldsm4(uint32_t* r, uint32_t a) {
    asm volatile("ldmatrix.sync.aligned.m8n8.x4.shared.b16 {%0,%1,%2,%3}, [%4];"
                 : "=r"(r[0]), "=r"(r[1]), "=r"(r[2]), "=r"(r[3]) : "r"(a));
}
__device__ __forceinline__ void ldsm4t(uint32_t* r, uint32_t a) {
    asm volatile("ldmatrix.sync.aligned.m8n8.x4.trans.shared.b16 {%0,%1,%2,%3}, [%4];"
                 : "=r"(r[0]), "=r"(r[1]), "=r"(r[2]), "=r"(r[3]) : "r"(a));
}
__device__ __forceinline__ void mma16816(float* c, const uint32_t* a, const uint32_t* b) {
    asm volatile("mma.sync.aligned.m16n8k16.row.col.f32.f16.f16.f32 "
                 "{%0,%1,%2,%3}, {%4,%5,%6,%7}, {%8,%9}, {%0,%1,%2,%3};"
                 : "+f"(c[0]), "+f"(c[1]), "+f"(c[2]), "+f"(c[3])
                 : "r"(a[0]), "r"(a[1]), "r"(a[2]), "r"(a[3]), "r"(b[0]), "r"(b[1]));
}
#define CPASYNC16(s, g) asm volatile("cp.async.cg.shared.global [%0], [%1], 16;" :: "r"(s), "l"(g))
#define CPCOMMIT()      asm volatile("cp.async.commit_group;" ::: "memory")
#define CPWAIT0()       asm volatile("cp.async.wait_group 0;" ::: "memory")

// ---- pre-pass: K,V fp32 -> fp16 hi rows in scratch ----
__global__ __launch_bounds__(256)
void convert_kv(const float* __restrict__ Kg, const float* __restrict__ Vg) {
    const int idx = blockIdx.x * 256 + threadIdx.x;
    const int row = idx >> 5, f4 = idx & 31;
    const int bh = row >> 11, s = row & 2047;
    const size_t src = (size_t)s * ROWSTRIDE + bh * HD + f4 * 4;
    float4 k = *(const float4*)(Kg + src);
    float4 v = *(const float4*)(Vg + src);
    *(uint2*)(KH + (size_t)row * 256 + f4 * 8) =
        make_uint2(pack2h(k.x, k.y), pack2h(k.z, k.w));
    *(uint2*)(VH + (size_t)row * 256 + f4 * 8) =
        make_uint2(pack2h(v.x, v.y), pack2h(v.z, v.w));
}

__device__ __forceinline__ void issue_tile(const unsigned char* scratch, uint32_t sb,
                                           uint32_t smbase, int bh, int g0, int tid) {
#pragma unroll
    for (int i = 0; i < 8; i++) {
        const int c = tid + NT * i, row = c >> 4, f4 = c & 15;
        CPASYNC16(sb + smbase + row * TSTR + f4 * 16,
                  scratch + (((size_t)(bh * SQ + g0 + row)) << 8) + f4 * 16);
    }
}

__global__ __launch_bounds__(NT, 2)
void attn_hmma(const float* __restrict__ Qg, const float* __restrict__ Bias,
               float* __restrict__ Out) {
    extern __shared__ char smem[];
    const uint32_t sb = s2u(smem);
    const int tid = threadIdx.x, lane = tid & 31, warp = tid >> 5;
    const int m0 = warp * 16;
    const int tile = 31 - (int)blockIdx.x;    // heavy tiles first
    const int head = blockIdx.y, batch = blockIdx.z;
    const int q0 = tile * BM, seg0 = (q0 / SEG) * SEG;
    const int bh = batch * NHD + head;
    const int base = bh * HD;
    const int nkt = (q0 - seg0) / BN + 1;

    // ---- prologue: K0 cp.async; Q hi -> staging (aliases V bufs) -> frags ----
    issue_tile(KH, sb, SM_K, bh, seg0, tid);
    CPCOMMIT();
#pragma unroll
    for (int i = 0; i < 16; i++) {
        const int idx = tid + NT * i, row = idx >> 5, f4 = idx & 31;
        const float4 v = *(const float4*)(Qg + (size_t)(q0 + row) * ROWSTRIDE + base + f4 * 4);
        *(uint2*)(smem + SM_QSTG + row * TSTR + f4 * 8) =
            make_uint2(pack2h(v.x, v.y), pack2h(v.z, v.w));
    }
    __syncthreads();
    uint32_t qH[8][4];
#pragma unroll
    for (int ks = 0; ks < 8; ks++) {
        const uint32_t ad = sb + SM_QSTG + (m0 + (lane & 15)) * TSTR
                          + ks * 32 + (lane >> 4) * 16;
        ldsm4(qH[ks], ad);
    }
    __syncthreads();                          // staging free -> V buffers usable

    float o[16][4];
#pragma unroll
    for (int j = 0; j < 16; j++)
#pragma unroll
        for (int r = 0; r < 4; r++) o[j][r] = 0.f;
    float lsum0 = 0.f, lsum1 = 0.f;
    uint32_t pFp[4][4];                       // P frags of tile kt-1 (persist)

    const int r0 = lane >> 2, q2 = (lane & 3) * 2;
    const int qr0 = q0 + m0 + r0, qr1 = qr0 + 8;
    const float* bp0 = Bias + (size_t)batch * SQ * SQ + (size_t)qr0 * SQ;
    const float* bp1 = Bias + (size_t)batch * SQ * SQ + (size_t)qr1 * SQ;

    for (int kt = 0; kt < nkt; kt++) {
        const int k0 = seg0 + kt * BN;
        const uint32_t kb  = SM_K + (kt & 1) * TILE_H;
        const uint32_t vbp = SM_V + ((kt + 1) & 1) * TILE_H;   // V(kt-1)

        CPWAIT0();           // K(kt) and V(kt-1) resident
        __syncthreads();     // all warps past reads of buffers being overwritten

        if (kt + 1 < nkt)
            issue_tile(KH, sb, SM_K + ((kt + 1) & 1) * TILE_H, bh, k0 + BN, tid);
        issue_tile(VH, sb, SM_V + (kt & 1) * TILE_H, bh, k0, tid);   // V(kt)
        CPCOMMIT();

        float c[8][4];
#pragma unroll
        for (int f = 0; f < 8; f++)
#pragma unroll
            for (int r = 0; r < 4; r++) c[f][r] = 0.f;

        if (kt == 0) {
            // ---- QK only (no pending PV) ----
#pragma unroll
            for (int ks = 0; ks < 8; ks++) {
                uint32_t bH[4][4];
#pragma unroll
                for (int g = 0; g < 4; g++) {
                    const uint32_t bd = sb + kb
                        + (g * 16 + ((lane >> 4) & 1) * 8 + (lane & 7)) * TSTR
                        + ks * 32 + ((lane >> 3) & 1) * 16;
                    ldsm4(bH[g], bd);
                }
#pragma unroll
                for (int g = 0; g < 4; g++) {
                    mma16816(c[2 * g],     qH[ks], &bH[g][0]);
                    mma16816(c[2 * g + 1], qH[ks], &bH[g][2]);
                }
            }
        } else {
            // ---- QK(kt) interleaved with PV(kt-1) ----
#pragma unroll
            for (int ks = 0; ks < 8; ks++) {
                uint32_t bH[4][4];
#pragma unroll
                for (int g = 0; g < 4; g++) {
                    const uint32_t bd = sb + kb
                        + (g * 16 + ((lane >> 4) & 1) * 8 + (lane & 7)) * TSTR
                        + ks * 32 + ((lane >> 3) & 1) * 16;
                    ldsm4(bH[g], bd);
                }
                const int kk  = ks >> 1;
                const int vq0 = (ks & 1) * 2;
                const uint32_t vdb = sb + vbp
                    + (kk * 16 + ((lane >> 3) & 1) * 8 + (lane & 7)) * TSTR;
                uint32_t vA[4], vB[4];
                ldsm4t(vA, vdb + ((2 * vq0)     * 16 + (lane >> 4) * 8) * 2);
                ldsm4t(vB, vdb + ((2 * vq0 + 1) * 16 + (lane >> 4) * 8) * 2);
#pragma unroll
                for (int g = 0; g < 4; g++) {
                    mma16816(c[2 * g],     qH[ks], &bH[g][0]);
                    mma16816(c[2 * g + 1], qH[ks], &bH[g][2]);
                }
                mma16816(o[4 * vq0],     pFp[kk], &vA[0]);
                mma16816(o[4 * vq0 + 1], pFp[kk], &vA[2]);
                mma16816(o[4 * vq0 + 2], pFp[kk], &vB[0]);
                mma16816(o[4 * vq0 + 3], pFp[kk], &vB[2]);
                uint32_t vC[4], vD[4];
                ldsm4t(vC, vdb + ((2 * vq0 + 2) * 16 + (lane >> 4) * 8) * 2);
                ldsm4t(vD, vdb + ((2 * vq0 + 3) * 16 + (lane >> 4) * 8) * 2);
                mma16816(o[4 * vq0 + 4], pFp[kk], &vC[0]);
                mma16816(o[4 * vq0 + 5], pFp[kk], &vC[2]);
                mma16816(o[4 * vq0 + 6], pFp[kk], &vD[0]);
                mma16816(o[4 * vq0 + 7], pFp[kk], &vD[2]);
            }
        }

        // ---- softmax + causal + bias; p rounded ONCE to fp16 -> pFp ----
#pragma unroll
        for (int f = 0; f < 8; f++) {
            const int col = k0 + f * 8 + q2;
            const float2 b0 = __ldg((const float2*)(bp0 + col));
            const float2 b1 = __ldg((const float2*)(bp1 + col));
            const float p0 = (col     <= qr0) ? __expf(c[f][0] * ATTN_SCALE + b0.x) : 0.f;
            const float p1 = (col + 1 <= qr0) ? __expf(c[f][1] * ATTN_SCALE + b0.y) : 0.f;
            const float p2 = (col     <= qr1) ? __expf(c[f][2] * ATTN_SCALE + b1.x) : 0.f;
            const float p3 = (col + 1 <= qr1) ? __expf(c[f][3] * ATTN_SCALE + b1.y) : 0.f;
            const __half h0 = __float2half_rn(p0), h1 = __float2half_rn(p1);
            const __half h2 = __float2half_rn(p2), h3 = __float2half_rn(p3);
            lsum0 += __half2float(h0) + __half2float(h1);
            lsum1 += __half2float(h2) + __half2float(h3);
            const int t = f >> 1, half = f & 1;
            pFp[t][2 * half + 0] = ((uint32_t)__half_as_ushort(h1) << 16) | __half_as_ushort(h0);
            pFp[t][2 * half + 1] = ((uint32_t)__half_as_ushort(h3) << 16) | __half_as_ushort(h2);
        }
    }

    // ---- epilogue: drain PV(nkt-1) ----
    CPWAIT0();           // V(nkt-1) resident (all threads' groups)
    __syncthreads();     // other threads' cp.async writes visible
    {
        const uint32_t vb = SM_V + ((nkt - 1) & 1) * TILE_H;
#pragma unroll
        for (int kk = 0; kk < 4; kk++) {
            const uint32_t vdb = sb + vb
                + (kk * 16 + ((lane >> 3) & 1) * 8 + (lane & 7)) * TSTR;
#pragma unroll
            for (int vq = 0; vq < 4; vq++) {
                const int vp0 = 2 * vq, vp1 = 2 * vq + 1;
                uint32_t vH0[4], vH1[4];
                ldsm4t(vH0, vdb + (vp0 * 16 + (lane >> 4) * 8) * 2);
                ldsm4t(vH1, vdb + (vp1 * 16 + (lane >> 4) * 8) * 2);
                mma16816(o[2 * vp0],     pFp[kk], &vH0[0]);
                mma16816(o[2 * vp0 + 1], pFp[kk], &vH0[2]);
                mma16816(o[2 * vp1],     pFp[kk], &vH1[0]);
                mma16816(o[2 * vp1 + 1], pFp[kk], &vH1[2]);
            }
        }
    }

    // ---- finalize: row sums warp-local ----
    lsum0 += __shfl_xor_sync(0xffffffffu, lsum0, 1);
    lsum0 += __shfl_xor_sync(0xffffffffu, lsum0, 2);
    lsum1 += __shfl_xor_sync(0xffffffffu, lsum1, 1);
    lsum1 += __shfl_xor_sync(0xffffffffu, lsum1, 2);
    const float inv0 = 1.0f / lsum0, inv1 = 1.0f / lsum1;

    float* op0 = Out + ((size_t)bh * SQ + qr0) * HD + q2;
    float* op1 = Out + ((size_t)bh * SQ + qr1) * HD + q2;
#pragma unroll
    for (int vp = 0; vp < 8; vp++) {
#pragma unroll
        for (int h = 0; h < 2; h++) {
            const int col = vp * 16 + h * 8;
            float2 w0, w1;
            w0.x = o[2 * vp + h][0] * inv0; w0.y = o[2 * vp + h][1] * inv0;
            w1.x = o[2 * vp + h][2] * inv1; w1.y = o[2 * vp + h][3] * inv1;
            *(float2*)(op0 + col) = w0;
            *(float2*)(op1 + col) = w1;
        }
    }
}

extern "C" void kernel_launch(void* const* d_in, const int* in_sizes, int n_in,
                              void* d_out, int out_size) {
    const float* Q    = (const float*)d_in[0];
    const float* K    = (const float*)d_in[1];
    const float* V    = (const float*)d_in[2];
    const float* Bias = (const float*)d_in[3];
    float* O = (float*)d_out;

    convert_kv<<<8192, 256>>>(K, V);

    cudaFuncSetAttribute(attn_hmma, cudaFuncAttributeMaxDynamicSharedMemorySize, SMEM_TOTAL);
    dim3 grid(SQ / BM, NHD, NB);   // (32,16,2) = 1024 CTAs
    attn_hmma<<<grid, NT, SMEM_TOTAL>>>(Q, Bias, O);
}

// round 17
// speedup vs baseline: 1.1734x; 1.1734x over previous
#include <cuda_runtime.h>
#include <cuda_fp16.h>
#include <cstdint>

// Packed-varlen (SEG=1024) causal attention + additive bias, fp32 I/O.
// Round 13: round-11 structure (best: 118.8us) + faster prepass (4 rows/thread),
// bias prefetched into regs before QK, causal predicates only on the diagonal
// k-tile, lsum accumulated from unrounded p (drops 32 h2f per warp-iter).

#define SQ   2048
#define NB   2
#define NHD  16
#define HD   128
#define SEG  1024
#define BM   64
#define BN   64
#define NT   128
#define ROWSTRIDE (NB*NHD*HD)
#define ATTN_SCALE 0.08838834764831845f

// scratch: fp16 hi rows, 256B per (b,h,s)
__device__ __align__(256) static unsigned char KH[(size_t)NB * NHD * SQ * 256];
__device__ __align__(256) static unsigned char VH[(size_t)NB * NHD * SQ * 256];

#define TSTR 272
#define TILE_H 17408
#define SM_K 0                 // K double buffer: 2 x 17408
#define SM_V 34816             // V double buffer: 2 x 17408 (Q staging aliases)
#define SM_QSTG 34816
#define SMEM_TOTAL 69632       // 68 KB -> 2 CTAs/SM

__device__ __forceinline__ uint32_t s2u(const void* p) {
    uint32_t a;
    asm("{ .reg .u64 t; cvta.to.shared.u64 t, %1; cvt.u32.u64 %0, t; }" : "=r"(a) : "l"(p));
    return a;
}
__device__ __forceinline__ uint32_t pack2h(float a, float b) {
    __half ah = __float2half_rn(a);
    __half bh = __float2half_rn(b);
    return ((uint32_t)__half_as_ushort(bh) << 16) | __half_as_ushort(ah);
}
__device__ __forceinline__ void ldsm4(uint32_t* r, uint32_t a) {
    asm volatile("ldmatrix.sync.aligned.m8n8.x4.shared.b16 {%0,%1,%2,%3}, [%4];"
                 : "=r"(r[0]), "=r"(r[1]), "=r"(r[2]), "=r"(r[3]) : "r"(a));
}
__device__ __forceinline__ void ldsm4t(uint32_t* r, uint32_t a) {
    asm volatile("ldmatrix.sync.aligned.m8n8.x4.trans.shared.b16 {%0,%1,%2,%3}, [%4];"
                 : "=r"(r[0]), "=r"(r[1]), "=r"(r[2]), "=r"(r[3]) : "r"(a));
}
__device__ __forceinline__ void mma16816(float* c, const uint32_t* a, const uint32_t* b) {
    asm volatile("mma.sync.aligned.m16n8k16.row.col.f32.f16.f16.f32 "
                 "{%0,%1,%2,%3}, {%4,%5,%6,%7}, {%8,%9}, {%0,%1,%2,%3};"
                 : "+f"(c[0]), "+f"(c[1]), "+f"(c[2]), "+f"(c[3])
                 : "r"(a[0]), "r"(a[1]), "r"(a[2]), "r"(a[3]), "r"(b[0]), "r"(b[1]));
}
#define CPASYNC16(s, g) asm volatile("cp.async.cg.shared.global [%0], [%1], 16;" :: "r"(s), "l"(g))
#define CPCOMMIT()      asm volatile("cp.async.commit_group;" ::: "memory")
#define CPWAIT0()       asm volatile("cp.async.wait_group 0;" ::: "memory")

// ---- pre-pass: K,V fp32 -> fp16 hi rows; 4 rows per thread (MLP) ----
__global__ __launch_bounds__(256)
void convert_kv(const float* __restrict__ Kg, const float* __restrict__ Vg) {
    const int tbase = blockIdx.x * 256 + threadIdx.x;
#pragma unroll
    for (int i = 0; i < 4; i++) {
        const int idx = tbase + i * 524288;      // 2048 blocks x 256 thr x 4
        const int row = idx >> 5, f4 = idx & 31;
        const int bh = row >> 11, s = row & 2047;
        const size_t src = (size_t)s * ROWSTRIDE + bh * HD + f4 * 4;
        float4 k = *(const float4*)(Kg + src);
        float4 v = *(const float4*)(Vg + src);
        *(uint2*)(KH + (size_t)row * 256 + f4 * 8) =
            make_uint2(pack2h(k.x, k.y), pack2h(k.z, k.w));
        *(uint2*)(VH + (size_t)row * 256 + f4 * 8) =
            make_uint2(pack2h(v.x, v.y), pack2h(v.z, v.w));
    }
}

// cp.async one 64-row fp16 tile (256B rows) into smem at smbase.
__device__ __forceinline__ void issue_tile(const unsigned char* scratch, uint32_t sb,
                                           uint32_t smbase, int bh, int g0, int tid) {
#pragma unroll
    for (int i = 0; i < 8; i++) {
        const int c = tid + NT * i, row = c >> 4, f4 = c & 15;
        CPASYNC16(sb + smbase + row * TSTR + f4 * 16,
                  scratch + (((size_t)(bh * SQ + g0 + row)) << 8) + f4 * 16);
    }
}

__global__ __launch_bounds__(NT, 2)
void attn_hmma(const float* __restrict__ Qg, const float* __restrict__ Bias,
               float* __restrict__ Out) {
    extern __shared__ char smem[];
    const uint32_t sb = s2u(smem);
    const int tid = threadIdx.x, lane = tid & 31, warp = tid >> 5;
    const int m0 = warp * 16;
    const int tile = 31 - (int)blockIdx.x;    // heavy tiles first
    const int head = blockIdx.y, batch = blockIdx.z;
    const int q0 = tile * BM, seg0 = (q0 / SEG) * SEG;
    const int bh = batch * NHD + head;
    const int base = bh * HD;
    const int nkt = (q0 - seg0) / BN + 1;

    // ---- prologue: K0 cp.async; Q hi -> staging (aliases V bufs) -> frags ----
    issue_tile(KH, sb, SM_K, bh, seg0, tid);
    CPCOMMIT();
#pragma unroll
    for (int i = 0; i < 16; i++) {
        const int idx = tid + NT * i, row = idx >> 5, f4 = idx & 31;
        const float4 v = *(const float4*)(Qg + (size_t)(q0 + row) * ROWSTRIDE + base + f4 * 4);
        *(uint2*)(smem + SM_QSTG + row * TSTR + f4 * 8) =
            make_uint2(pack2h(v.x, v.y), pack2h(v.z, v.w));
    }
    __syncthreads();
    uint32_t qH[8][4];                        // persistent Q hi fragments
#pragma unroll
    for (int ks = 0; ks < 8; ks++) {
        const uint32_t ad = sb + SM_QSTG + (m0 + (lane & 15)) * TSTR
                          + ks * 32 + (lane >> 4) * 16;
        ldsm4(qH[ks], ad);
    }
    __syncthreads();                          // staging free -> V buffers usable
    issue_tile(VH, sb, SM_V, bh, seg0, tid);  // V0
    CPCOMMIT();

    float o[16][4];
#pragma unroll
    for (int j = 0; j < 16; j++)
#pragma unroll
        for (int r = 0; r < 4; r++) o[j][r] = 0.f;
    float lsum0 = 0.f, lsum1 = 0.f;

    const int r0 = lane >> 2, q2 = (lane & 3) * 2;
    const int qr0 = q0 + m0 + r0, qr1 = qr0 + 8;
    const float* bp0 = Bias + (size_t)batch * SQ * SQ + (size_t)qr0 * SQ;
    const float* bp1 = Bias + (size_t)batch * SQ * SQ + (size_t)qr1 * SQ;

    for (int kt = 0; kt < nkt; kt++) {
        const int k0 = seg0 + kt * BN;
        const uint32_t kb = SM_K + (kt & 1) * TILE_H;
        const uint32_t vb = SM_V + (kt & 1) * TILE_H;

        CPWAIT0();           // K(kt), V(kt) resident
        __syncthreads();     // all warps done reading the other buffers

        // ---- bias prefetch for this tile (hides L2 latency behind QK) ----
        float2 bb0[8], bb1[8];
#pragma unroll
        for (int f = 0; f < 8; f++) {
            const int col = k0 + f * 8 + q2;
            bb0[f] = __ldg((const float2*)(bp0 + col));
            bb1[f] = __ldg((const float2*)(bp1 + col));
        }

        if (kt + 1 < nkt) {  // prefetch K(kt+1), V(kt+1)
            const uint32_t nb = (kt + 1) & 1;
            issue_tile(KH, sb, SM_K + nb * TILE_H, bh, k0 + BN, tid);
            issue_tile(VH, sb, SM_V + nb * TILE_H, bh, k0 + BN, tid);
            CPCOMMIT();
        }

        // ---- S = Qh Kh^T : 1 product, 8 independent accumulators ----
        float c[8][4];
#pragma unroll
        for (int f = 0; f < 8; f++)
#pragma unroll
            for (int r = 0; r < 4; r++) c[f][r] = 0.f;

#pragma unroll
        for (int ks = 0; ks < 8; ks++) {
            uint32_t bH[4][4];
#pragma unroll
            for (int g = 0; g < 4; g++) {
                const uint32_t bd = sb + kb + (g * 16 + ((lane >> 4) & 1) * 8 + (lane & 7)) * TSTR
                                  + ks * 32 + ((lane >> 3) & 1) * 16;
                ldsm4(bH[g], bd);
            }
#pragma unroll
            for (int g = 0; g < 4; g++) {
                mma16816(c[2 * g],     qH[ks], &bH[g][0]);
                mma16816(c[2 * g + 1], qH[ks], &bH[g][2]);
            }
        }

        // ---- softmax; causal predicates only on the diagonal tile ----
        uint32_t pF[4][4];
        if (kt < nkt - 1) {
#pragma unroll
            for (int f = 0; f < 8; f++) {
                const float p0 = __expf(c[f][0] * ATTN_SCALE + bb0[f].x);
                const float p1 = __expf(c[f][1] * ATTN_SCALE + bb0[f].y);
                const float p2 = __expf(c[f][2] * ATTN_SCALE + bb1[f].x);
                const float p3 = __expf(c[f][3] * ATTN_SCALE + bb1[f].y);
                lsum0 += p0 + p1;
                lsum1 += p2 + p3;
                const int t = f >> 1, half = f & 1;
                pF[t][2 * half + 0] = pack2h(p0, p1);
                pF[t][2 * half + 1] = pack2h(p2, p3);
            }
        } else {
#pragma unroll
            for (int f = 0; f < 8; f++) {
                const int col = k0 + f * 8 + q2;
                const float p0 = (col     <= qr0) ? __expf(c[f][0] * ATTN_SCALE + bb0[f].x) : 0.f;
                const float p1 = (col + 1 <= qr0) ? __expf(c[f][1] * ATTN_SCALE + bb0[f].y) : 0.f;
                const float p2 = (col     <= qr1) ? __expf(c[f][2] * ATTN_SCALE + bb1[f].x) : 0.f;
                const float p3 = (col + 1 <= qr1) ? __expf(c[f][3] * ATTN_SCALE + bb1[f].y) : 0.f;
                lsum0 += p0 + p1;
                lsum1 += p2 + p3;
                const int t = f >> 1, half = f & 1;
                pF[t][2 * half + 0] = pack2h(p0, p1);
                pF[t][2 * half + 1] = pack2h(p2, p3);
            }
        }

        // ---- O += p~ Vh : 1 product, V columns in pairs ----
#pragma unroll
        for (int kk = 0; kk < 4; kk++) {
            const uint32_t vdb = sb + vb + (kk * 16 + ((lane >> 3) & 1) * 8 + (lane & 7)) * TSTR;
#pragma unroll
            for (int vq = 0; vq < 4; vq++) {
                const int vp0 = 2 * vq, vp1 = 2 * vq + 1;
                uint32_t vH0[4], vH1[4];
                ldsm4t(vH0, vdb + (vp0 * 16 + (lane >> 4) * 8) * 2);
                ldsm4t(vH1, vdb + (vp1 * 16 + (lane >> 4) * 8) * 2);
                mma16816(o[2 * vp0],     pF[kk], &vH0[0]);
                mma16816(o[2 * vp0 + 1], pF[kk], &vH0[2]);
                mma16816(o[2 * vp1],     pF[kk], &vH1[0]);
                mma16816(o[2 * vp1 + 1], pF[kk], &vH1[2]);
            }
        }
    }

    // ---- finalize: row sums warp-local ----
    lsum0 += __shfl_xor_sync(0xffffffffu, lsum0, 1);
    lsum0 += __shfl_xor_sync(0xffffffffu, lsum0, 2);
    lsum1 += __shfl_xor_sync(0xffffffffu, lsum1, 1);
    lsum1 += __shfl_xor_sync(0xffffffffu, lsum1, 2);
    const float inv0 = 1.0f / lsum0, inv1 = 1.0f / lsum1;

    float* op0 = Out + ((size_t)bh * SQ + qr0) * HD + q2;
    float* op1 = Out + ((size_t)bh * SQ + qr1) * HD + q2;
#pragma unroll
    for (int vp = 0; vp < 8; vp++) {
#pragma unroll
        for (int h = 0; h < 2; h++) {
            const int col = vp * 16 + h * 8;
            float2 w0, w1;
            w0.x = o[2 * vp + h][0] * inv0; w0.y = o[2 * vp + h][1] * inv0;
            w1.x = o[2 * vp + h][2] * inv1; w1.y = o[2 * vp + h][3] * inv1;
            *(float2*)(op0 + col) = w0;
            *(float2*)(op1 + col) = w1;
        }
    }
}

extern "C" void kernel_launch(void* const* d_in, const int* in_sizes, int n_in,
                              void* d_out, int out_size) {
    const float* Q    = (const float*)d_in[0];
    const float* K    = (const float*)d_in[1];
    const float* V    = (const float*)d_in[2];
    const float* Bias = (const float*)d_in[3];
    float* O = (float*)d_out;

    convert_kv<<<2048, 256>>>(K, V);

    cudaFuncSetAttribute(attn_hmma, cudaFuncAttributeMaxDynamicSharedMemorySize, SMEM_TOTAL);
    dim3 grid(SQ / BM, NHD, NB);   // (32,16,2) = 1024 CTAs
    attn_hmma<<<grid, NT, SMEM_TOTAL>>>(Q, Bias, O);
}